// round 9
// baseline (speedup 1.0000x reference)
#include <cuda_runtime.h>
#include <cuda_bf16.h>
#include <cuda_fp16.h>
#include <math.h>
#include <stdint.h>

#define NS   16
#define LL   256
#define HH   128
#define LAMF 20.0f
#define EPSF 1e-8f
#define NARC (NS * LL * LL)
#define NCHUNK 8192
#define MLP_GRID 148
#define COST_GRID (NS * 36)

// -------- scratch --------
__device__ __align__(16) float g_C [NARC];
__device__ unsigned int g_maxabs[NS];
__device__ __align__(16) __nv_bfloat16 g_Kph [NARC];
__device__ __align__(16) __nv_bfloat16 g_Kpl [NARC];
__device__ __align__(16) __nv_bfloat16 g_KMph[NARC];
__device__ __align__(16) __nv_bfloat16 g_KMpl[NARC];

// ================= PTX helpers (baseline sm_103) =================
__device__ __forceinline__ uint32_t smem_u32(const void* p) {
    uint32_t a;
    asm("{ .reg .u64 t; cvta.to.shared.u64 t, %1; cvt.u32.u64 %0, t; }" : "=r"(a) : "l"(p));
    return a;
}
#define MBAR_INIT(addr, cnt) \
    asm volatile("mbarrier.init.shared.b64 [%0], %1;" :: "r"(addr), "r"(cnt) : "memory")
#define MBAR_ARRIVE(addr) \
    asm volatile("mbarrier.arrive.shared.b64 _, [%0];" :: "r"(addr) : "memory")
#define MBAR_WAIT(addr, ph) do { \
    uint32_t _m = (addr); uint32_t _p = (ph); uint32_t _d; \
    asm volatile("{\n\t.reg .pred p;\n\tmbarrier.try_wait.parity.acquire.cta.shared::cta.b64 p, [%1], %2;\n\tselp.b32 %0, 1, 0, p;\n\t}" \
        : "=r"(_d) : "r"(_m), "r"(_p) : "memory"); \
    if (!_d) { \
        asm volatile("{\n\t.reg .pred P1;\n\tWL_%=:\n\tmbarrier.try_wait.parity.acquire.cta.shared::cta.b64 P1, [%0], %1, 0x989680;\n\t@P1 bra.uni WD_%=;\n\tbra.uni WL_%=;\n\tWD_%=:\n\t}" \
            :: "r"(_m), "r"(_p) : "memory"); \
    } } while (0)
#define LDSM_X4(r, addr) \
    asm volatile("ldmatrix.sync.aligned.m8n8.x4.shared.b16 {%0,%1,%2,%3}, [%4];" \
        : "=r"((r)[0]), "=r"((r)[1]), "=r"((r)[2]), "=r"((r)[3]) : "r"(addr))
#define LDSM_X4T(r, addr) \
    asm volatile("ldmatrix.sync.aligned.m8n8.x4.trans.shared.b16 {%0,%1,%2,%3}, [%4];" \
        : "=r"((r)[0]), "=r"((r)[1]), "=r"((r)[2]), "=r"((r)[3]) : "r"(addr))
#define MMA_BF16(d, a, b) \
    asm volatile("mma.sync.aligned.m16n8k16.row.col.f32.bf16.bf16.f32 " \
        "{%0,%1,%2,%3}, {%4,%5,%6,%7}, {%8,%9}, {%0,%1,%2,%3};" \
        : "+f"((d)[0]), "+f"((d)[1]), "+f"((d)[2]), "+f"((d)[3]) \
        : "r"((a)[0]), "r"((a)[1]), "r"((a)[2]), "r"((a)[3]), "r"((b)[0]), "r"((b)[1]))
#define MMA_F16(d, a, b) \
    asm volatile("mma.sync.aligned.m16n8k16.row.col.f32.f16.f16.f32 " \
        "{%0,%1,%2,%3}, {%4,%5,%6,%7}, {%8,%9}, {%0,%1,%2,%3};" \
        : "+f"((d)[0]), "+f"((d)[1]), "+f"((d)[2]), "+f"((d)[3]) \
        : "r"((a)[0]), "r"((a)[1]), "r"((a)[2]), "r"((a)[3]), "r"((b)[0]), "r"((b)[1]))
__device__ __forceinline__ void sts32(uint32_t addr, uint32_t v) {
    asm volatile("st.shared.b32 [%0], %1;" :: "r"(addr), "r"(v) : "memory");
}
__device__ __forceinline__ float lds32f(uint32_t addr) {
    float v; asm volatile("ld.shared.f32 %0, [%1];" : "=f"(v) : "r"(addr)); return v;
}
__device__ __forceinline__ void sts32f(uint32_t addr, float v) {
    asm volatile("st.shared.f32 [%0], %1;" :: "r"(addr), "f"(v) : "memory");
}
#define CVT2BF(dst, hi, lo) \
    asm("cvt.rn.bf16x2.f32 %0, %1, %2;" : "=r"(dst) : "f"(hi), "f"(lo))
__device__ __forceinline__ uint32_t pack_bf16(__nv_bfloat16 a, __nv_bfloat16 b) {
    __nv_bfloat162 p = __halves2bfloat162(a, b);
    return *reinterpret_cast<uint32_t*>(&p);
}
__device__ __forceinline__ uint32_t pack_h16(__half a, __half b) {
    __half2 p = __halves2half2(a, b);
    return *reinterpret_cast<uint32_t*>(&p);
}
__device__ __forceinline__ float ftanh(float x) {
    float r; asm("tanh.approx.f32 %0, %1;" : "=f"(r) : "f"(x)); return r;
}

// -------- init --------
__global__ void init_kernel(float* __restrict__ loss) {
    int idx = threadIdx.x;
    if (idx < NS) g_maxabs[idx] = 0u;
    if (idx == 0) *loss = 0.0f;
}

// ============ MERGED: MLP CTAs (0..147) + cost CTAs (148..723) ============
#define PITCHB  272
#define ATILE   34816
#define SP_OFF  64
#define B1S_OFF 1088
#define W2S_OFF 1600
#define WHI_OFF 2176
#define A_OFF   36992
#define MLP_SMEM 106624

__global__ void __launch_bounds__(384, 1) merged_kernel(
    const float* __restrict__ f,  const float* __restrict__ W1,
    const float* __restrict__ b1, const float* __restrict__ W2,
    const float* __restrict__ b2, float* __restrict__ scores)
{
    extern __shared__ __align__(1024) char smem[];
    const int tid = threadIdx.x;

    if (blockIdx.x >= MLP_GRID) {
        // ================= COST ROLE =================
        const int cb = blockIdx.x - MLP_GRID;
        const int n = cb / 36;
        int tt = cb % 36, bi = 0;
        while (tt >= 8 - bi) { tt -= 8 - bi; bi++; }
        const int bj = bi + tt;
        const int w = tid >> 5, lane = tid & 31;
        const float* fn = f + (size_t)n * (LL * LL * HH);
        float* C = g_C + (size_t)n * (LL * LL);
        float lmax = 0.0f;
#pragma unroll 1
        for (int a0 = w * 4; a0 < 1024; a0 += 48) {
            int r = a0 >> 5, cc = a0 & 31;
            int i = bi * 32 + r;
            float4 x[4], y[4];
#pragma unroll
            for (int p = 0; p < 4; p++) {
                int j = bj * 32 + cc + p;
                if (j >= i) {
                    x[p] = __ldg((const float4*)(fn + (size_t)(i * LL + j) * HH) + lane);
                    y[p] = __ldg((const float4*)(fn + (size_t)(j * LL + i) * HH) + lane);
                } else {
                    x[p] = make_float4(0.f, 0.f, 0.f, 0.f);
                    y[p] = x[p];
                }
            }
            float s[4];
#pragma unroll
            for (int p = 0; p < 4; p++)
                s[p] = x[p].x * y[p].x + x[p].y * y[p].y + x[p].z * y[p].z + x[p].w * y[p].w;
#pragma unroll
            for (int o = 16; o > 0; o >>= 1) {
#pragma unroll
                for (int p = 0; p < 4; p++) s[p] += __shfl_xor_sync(0xffffffffu, s[p], o);
            }
            if (lane == 0) {
#pragma unroll
                for (int p = 0; p < 4; p++) {
                    int j = bj * 32 + cc + p;
                    if (j >= i) {
                        C[i * LL + j] = s[p];
                        C[j * LL + i] = s[p];
                        lmax = fmaxf(lmax, fabsf(s[p]));
                    }
                }
            }
        }
        if (lane == 0) atomicMax(&g_maxabs[n], __float_as_uint(lmax));
        return;
    }

    // ================= MLP ROLE =================
    const uint32_t sb = smem_u32(smem);
    if (tid == 0) {
        MBAR_INIT(sb + 16, 128); MBAR_INIT(sb + 24, 128);
        MBAR_INIT(sb + 32, 256); MBAR_INIT(sb + 40, 256);
    }
    for (int i = tid; i < 16384; i += 384) {
        int k = i >> 7, nn = i & 127;
        ((__half*)(smem + WHI_OFF))[k * 136 + nn] = __float2half_rn(W1[i]);
    }
    if (tid < 128) {
        ((float*)(smem + B1S_OFF))[tid] = b1[tid];
        ((float*)(smem + W2S_OFF))[tid] = W2[tid];
    }
    __syncthreads();

    if (tid >= 256) {
        const int ptid = tid - 256;
        int lc = 0;
        for (int chunk = blockIdx.x; chunk < NCHUNK; chunk += MLP_GRID, ++lc) {
            const int s = lc & 1;
            if (lc >= 2) MBAR_WAIT(sb + 32 + s * 8, ((lc >> 1) - 1) & 1);
            const float4* src = (const float4*)(f + (size_t)chunk * 16384);
            char* ahi = smem + A_OFF + s * ATILE;
#pragma unroll 4
            for (int q = 0; q < 32; q++) {
                int idx = q * 128 + ptid;
                float4 v = __ldg(src + idx);
                int row = idx >> 5, colq = (idx & 31) << 2;
                int off = row * PITCHB + colq * 2;
                *(uint2*)(ahi + off) = make_uint2(
                    pack_h16(__float2half_rn(v.x), __float2half_rn(v.y)),
                    pack_h16(__float2half_rn(v.z), __float2half_rn(v.w)));
            }
            MBAR_ARRIVE(sb + 16 + s * 8);
        }
    } else {
        const int lane = tid & 31, wid = tid >> 5;
        const int warpM = wid >> 1, warpN = wid & 1;
        const int t = lane & 3, g = lane >> 2;
        const int lr = lane & 15, lh = lane >> 4;
        const float b2v = __ldg(b2);
        const float* sh_b1 = (const float*)(smem + B1S_OFF);
        const float* sh_w2 = (const float*)(smem + W2S_OFF);
        float* sp = (float*)(smem + SP_OFF);
        const uint32_t a_off = (uint32_t)((warpM * 32 + lr) * PITCHB + lh * 16);
        const uint32_t b_off = (uint32_t)(lr * PITCHB + (warpN * 64 + lh * 8) * 2);

        int lc = 0;
        for (int chunk = blockIdx.x; chunk < NCHUNK; chunk += MLP_GRID, ++lc) {
            const int s = lc & 1;
            MBAR_WAIT(sb + 16 + s * 8, (lc >> 1) & 1);
            const uint32_t sa_hi = sb + A_OFF + s * ATILE;

            float D[2][8][4];
#pragma unroll
            for (int i = 0; i < 2; i++)
#pragma unroll
                for (int j = 0; j < 8; j++)
#pragma unroll
                    for (int q = 0; q < 4; q++) D[i][j][q] = 0.0f;

#pragma unroll
            for (int ks = 0; ks < 8; ks++) {
                uint32_t ah0[4], ah1[4];
                LDSM_X4(ah0, sa_hi + a_off + ks * 32);
                LDSM_X4(ah1, sa_hi + a_off + 16 * PITCHB + ks * 32);
                uint32_t bh[8][2];
#pragma unroll
                for (int p = 0; p < 4; p++) {
                    uint32_t r[4];
                    LDSM_X4T(r, sb + WHI_OFF + b_off + ks * (16 * PITCHB) + p * 32);
                    bh[2*p][0] = r[0]; bh[2*p][1] = r[1];
                    bh[2*p+1][0] = r[2]; bh[2*p+1][1] = r[3];
                }
#pragma unroll
                for (int nf = 0; nf < 8; nf++) {
                    MMA_F16(D[0][nf], ah0, bh[nf]);
                    MMA_F16(D[1][nf], ah1, bh[nf]);
                }
            }
            MBAR_ARRIVE(sb + 32 + s * 8);

            float out_lo[2], out_hi[2];
#pragma unroll
            for (int mf = 0; mf < 2; mf++) {
                float plo = 0.0f, phi = 0.0f;
#pragma unroll
                for (int nf = 0; nf < 8; nf++) {
                    int col = warpN * 64 + nf * 8 + 2 * t;
                    float b1a = sh_b1[col], b1b = sh_b1[col + 1];
                    float w2a = sh_w2[col], w2b = sh_w2[col + 1];
                    plo += ftanh(D[mf][nf][0] + b1a) * w2a + ftanh(D[mf][nf][1] + b1b) * w2b;
                    phi += ftanh(D[mf][nf][2] + b1a) * w2a + ftanh(D[mf][nf][3] + b1b) * w2b;
                }
                plo += __shfl_xor_sync(0xffffffffu, plo, 1);
                plo += __shfl_xor_sync(0xffffffffu, plo, 2);
                phi += __shfl_xor_sync(0xffffffffu, phi, 1);
                phi += __shfl_xor_sync(0xffffffffu, phi, 2);
                out_lo[mf] = plo; out_hi[mf] = phi;
            }
            const int par = lc & 1;
            if (warpN == 0 && t == 0) {
#pragma unroll
                for (int mf = 0; mf < 2; mf++) {
                    int row = warpM * 32 + mf * 16 + g;
                    sp[par * 128 + row]     = out_lo[mf];
                    sp[par * 128 + row + 8] = out_hi[mf];
                }
            }
            asm volatile("bar.sync 1, 256;" ::: "memory");
            if (warpN == 1 && t == 0) {
                float* so = scores + (size_t)chunk * 128;
#pragma unroll
                for (int mf = 0; mf < 2; mf++) {
                    int row = warpM * 32 + mf * 16 + g;
                    so[row]     = out_lo[mf] + sp[par * 128 + row]     + b2v;
                    so[row + 8] = out_hi[mf] + sp[par * 128 + row + 8] + b2v;
                }
            }
        }
    }
}

// -------- kexp: K=exp(-LAM*Cn), KM=K*Cn -> split bf16, MMA-A-permuted --------
__global__ void kexp_kernel() {
    int idx = blockIdx.x * blockDim.x + threadIdx.x;
    int n = idx >> 16;
    int r = (idx >> 8) & 255, k = idx & 255;
    float mx = __uint_as_float(g_maxabs[n]);
    float cn = g_C[idx] / (mx + EPSF);
    float kv = __expf(-LAMF * cn);
    float km = kv * cn;
    int mt = r >> 4, rl = r & 15, kt = k >> 4, kl = k & 15;
    int T   = ((rl & 7) << 2) + ((kl & 7) >> 1);
    int reg = (rl >> 3) + ((kl >> 3) << 1);
    int pofs = (n << 16) + (((mt << 4) + kt) << 8) + (T << 3) + (reg << 1) + (kl & 1);
    __nv_bfloat16 kh = __float2bfloat16(kv);
    __nv_bfloat16 mh = __float2bfloat16(km);
    g_Kph [pofs] = kh;
    g_Kpl [pofs] = __float2bfloat16(kv - __bfloat162float(kh));
    g_KMph[pofs] = mh;
    g_KMpl[pofs] = __float2bfloat16(km - __bfloat162float(mh));
}

// ============ fused Sinkhorn: 256 CTAs x 256 thr, 16 problems/CTA ============
// smem: XHI 0 (12288, pitch 48) | XLO 12288 | UN 24576 (pitch 17 fl) | CN 41984
//       RED 59392 | total 59456.  2 CTAs/SM.
#define SK_XHI 0
#define SK_XLO 12288
#define SK_UN  24576
#define SK_CN  41984
#define SK_RED 59392
#define SK_SMEM 59456
#define XPITCH 48

template<bool STORE_U>
__device__ __noinline__ void sink_phase(
    const uint4* __restrict__ Ah, const uint4* __restrict__ Al,
    uint32_t xhi, uint32_t xlo, uint32_t nmb, int w, int lane)
{
    float D[2][2][4];
#pragma unroll
    for (int i = 0; i < 2; i++)
#pragma unroll
        for (int j = 0; j < 2; j++)
#pragma unroll
            for (int q = 0; q < 4; q++) D[i][j][q] = 0.0f;

    const int lr = lane & 15, lh = lane >> 4;
    const uint32_t bhb = xhi + lr * XPITCH + lh * 16;
    const uint32_t blb = xlo + lr * XPITCH + lh * 16;
#pragma unroll 4
    for (int kt = 0; kt < 16; kt++) {
        uint4 ah0 = Ah[(size_t)(w * 32 + kt) * 32 + lane];
        uint4 ah1 = Ah[(size_t)(w * 32 + 16 + kt) * 32 + lane];
        uint4 al0 = Al[(size_t)(w * 32 + kt) * 32 + lane];
        uint4 al1 = Al[(size_t)(w * 32 + 16 + kt) * 32 + lane];
        uint32_t bh[2][2], bl[2][2], r[4];
        LDSM_X4T(r, bhb + kt * (16 * XPITCH));
        bh[0][0] = r[0]; bh[0][1] = r[1]; bh[1][0] = r[2]; bh[1][1] = r[3];
        LDSM_X4T(r, blb + kt * (16 * XPITCH));
        bl[0][0] = r[0]; bl[0][1] = r[1]; bl[1][0] = r[2]; bl[1][1] = r[3];
#pragma unroll
        for (int nt = 0; nt < 2; nt++) {
            MMA_BF16(D[0][nt], ((uint32_t*)&ah0), bh[nt]);
            MMA_BF16(D[1][nt], ((uint32_t*)&ah1), bh[nt]);
            MMA_BF16(D[0][nt], ((uint32_t*)&al0), bh[nt]);
            MMA_BF16(D[1][nt], ((uint32_t*)&al1), bh[nt]);
            MMA_BF16(D[0][nt], ((uint32_t*)&ah0), bl[nt]);
            MMA_BF16(D[1][nt], ((uint32_t*)&ah1), bl[nt]);
        }
    }
    __syncthreads();
    const int rq = lane >> 2, cq = (lane & 3) * 2;
#pragma unroll
    for (int mt = 0; mt < 2; mt++) {
        int row = w * 32 + mt * 16 + rq;
#pragma unroll
        for (int nt = 0; nt < 2; nt++) {
            int col = nt * 8 + cq;
            uint32_t na = nmb + (row * 17 + col) * 4;
            uint32_t nb = nmb + ((row + 8) * 17 + col) * 4;
            float n0 = lds32f(na);
            float n1 = lds32f(na + 4);
            float n2 = lds32f(nb);
            float n3 = lds32f(nb + 4);
            float o0 = __fdividef(n0, D[mt][nt][0] + EPSF);
            float o1 = __fdividef(n1, D[mt][nt][1] + EPSF);
            float o2 = __fdividef(n2, D[mt][nt][2] + EPSF);
            float o3 = __fdividef(n3, D[mt][nt][3] + EPSF);
            uint32_t h01, h23, l01, l23;
            CVT2BF(h01, o1, o0);
            CVT2BF(h23, o3, o2);
            float l0 = o0 - __uint_as_float(h01 << 16);
            float l1 = o1 - __uint_as_float(h01 & 0xffff0000u);
            float l2 = o2 - __uint_as_float(h23 << 16);
            float l3 = o3 - __uint_as_float(h23 & 0xffff0000u);
            CVT2BF(l01, l1, l0);
            CVT2BF(l23, l3, l2);
            sts32(xhi + row * XPITCH + col * 2, h01);
            sts32(xhi + (row + 8) * XPITCH + col * 2, h23);
            sts32(xlo + row * XPITCH + col * 2, l01);
            sts32(xlo + (row + 8) * XPITCH + col * 2, l23);
            if (STORE_U) {   // write u back into the numerator slots (same addrs)
                sts32f(na, o0);
                sts32f(na + 4, o1);
                sts32f(nb, o2);
                sts32f(nb + 4, o3);
            }
        }
    }
    __syncthreads();
}

__global__ void __launch_bounds__(256, 2) sinkhorn_fused_kernel(
    const float* __restrict__ scores, const float* __restrict__ head,
    float* __restrict__ loss)
{
    extern __shared__ __align__(16) char smem[];
    const uint32_t sb = smem_u32(smem);
    const int tid = threadIdx.x, lane = tid & 31, w = tid >> 5;
    const int n = blockIdx.x >> 4, c0 = (blockIdx.x & 15) * 16;

    float* UN = (float*)(smem + SK_UN);
    float* CN = (float*)(smem + SK_CN);
    // ---- prologue: 16 rows of scores/head, transposed into UN/CN ----
#pragma unroll
    for (int q = 0; q < 2; q++) {
        int p = w * 2 + q;
        const float* row = scores + ((size_t)(n * 256 + c0 + p)) * 256;
        float4 v0 = *(const float4*)(row + lane * 4);
        float4 v1 = *(const float4*)(row + 128 + lane * 4);
        float m = fmaxf(fmaxf(fmaxf(v0.x, v0.y), fmaxf(v0.z, v0.w)),
                        fmaxf(fmaxf(v1.x, v1.y), fmaxf(v1.z, v1.w)));
#pragma unroll
        for (int o = 16; o > 0; o >>= 1) m = fmaxf(m, __shfl_xor_sync(0xffffffffu, m, o));
        float e[8];
        e[0] = __expf(v0.x - m); e[1] = __expf(v0.y - m);
        e[2] = __expf(v0.z - m); e[3] = __expf(v0.w - m);
        e[4] = __expf(v1.x - m); e[5] = __expf(v1.y - m);
        e[6] = __expf(v1.z - m); e[7] = __expf(v1.w - m);
        float sum = e[0]+e[1]+e[2]+e[3]+e[4]+e[5]+e[6]+e[7];
#pragma unroll
        for (int o = 16; o > 0; o >>= 1) sum += __shfl_xor_sync(0xffffffffu, sum, o);
        float inv = __fdividef(1.0f, sum);
#pragma unroll
        for (int k = 0; k < 4; k++) UN[(lane * 4 + k) * 17 + p]       = e[k] * inv;
#pragma unroll
        for (int k = 0; k < 4; k++) UN[(128 + lane * 4 + k) * 17 + p] = e[4 + k] * inv;

        const float* hrow = head + ((size_t)(n * 256 + c0 + p)) * 256;
        float4 h0 = *(const float4*)(hrow + lane * 4);
        float4 h1 = *(const float4*)(hrow + 128 + lane * 4);
        float he[8] = { h0.x + EPSF, h0.y + EPSF, h0.z + EPSF, h0.w + EPSF,
                        h1.x + EPSF, h1.y + EPSF, h1.z + EPSF, h1.w + EPSF };
        float hsum = he[0]+he[1]+he[2]+he[3]+he[4]+he[5]+he[6]+he[7];
#pragma unroll
        for (int o = 16; o > 0; o >>= 1) hsum += __shfl_xor_sync(0xffffffffu, hsum, o);
        float hinv = __fdividef(1.0f, hsum);
#pragma unroll
        for (int k = 0; k < 4; k++) CN[(lane * 4 + k) * 17 + p]       = he[k] * hinv;
#pragma unroll
        for (int k = 0; k < 4; k++) CN[(128 + lane * 4 + k) * 17 + p] = he[4 + k] * hinv;
    }
    const uint32_t HV = pack_bf16(__float2bfloat16(1.0f / 256.0f),
                                  __float2bfloat16(1.0f / 256.0f));
    for (int i = tid; i < 3072; i += 256) {
        ((uint32_t*)(smem + SK_XHI))[i] = HV;
        ((uint32_t*)(smem + SK_XLO))[i] = 0u;
    }
    __syncthreads();

    const uint4* Kh  = (const uint4*)g_Kph  + (size_t)n * 8192;
    const uint4* Kl  = (const uint4*)g_Kpl  + (size_t)n * 8192;
    const uint4* Mh  = (const uint4*)g_KMph + (size_t)n * 8192;
    const uint4* Ml  = (const uint4*)g_KMpl + (size_t)n * 8192;
    const uint32_t xhi = sb + SK_XHI, xlo = sb + SK_XLO;
    const uint32_t unb = sb + SK_UN, cnb = sb + SK_CN;

#pragma unroll 1
    for (int it = 0; it < 19; it++) {
        sink_phase<false>(Kh, Kl, xhi, xlo, cnb, w, lane);
        sink_phase<false>(Kh, Kl, xhi, xlo, unb, w, lane);
    }
    sink_phase<false>(Kh, Kl, xhi, xlo, cnb, w, lane);
    sink_phase<true >(Kh, Kl, xhi, xlo, unb, w, lane);   // u -> UN slots
    sink_phase<false>(Kh, Kl, xhi, xlo, cnb, w, lane);   // v in X

    // loss partial: sum u .* (KM @ v)
    float D[2][2][4];
#pragma unroll
    for (int i = 0; i < 2; i++)
#pragma unroll
        for (int j = 0; j < 2; j++)
#pragma unroll
            for (int q = 0; q < 4; q++) D[i][j][q] = 0.0f;
    {
        const int lr = lane & 15, lh = lane >> 4;
        const uint32_t bhb = xhi + lr * XPITCH + lh * 16;
        const uint32_t blb = xlo + lr * XPITCH + lh * 16;
#pragma unroll 4
        for (int kt = 0; kt < 16; kt++) {
            uint4 ah0 = Mh[(size_t)(w * 32 + kt) * 32 + lane];
            uint4 ah1 = Mh[(size_t)(w * 32 + 16 + kt) * 32 + lane];
            uint4 al0 = Ml[(size_t)(w * 32 + kt) * 32 + lane];
            uint4 al1 = Ml[(size_t)(w * 32 + 16 + kt) * 32 + lane];
            uint32_t bh[2][2], bl[2][2], r[4];
            LDSM_X4T(r, bhb + kt * (16 * XPITCH));
            bh[0][0] = r[0]; bh[0][1] = r[1]; bh[1][0] = r[2]; bh[1][1] = r[3];
            LDSM_X4T(r, blb + kt * (16 * XPITCH));
            bl[0][0] = r[0]; bl[0][1] = r[1]; bl[1][0] = r[2]; bl[1][1] = r[3];
#pragma unroll
            for (int nt = 0; nt < 2; nt++) {
                MMA_BF16(D[0][nt], ((uint32_t*)&ah0), bh[nt]);
                MMA_BF16(D[1][nt], ((uint32_t*)&ah1), bh[nt]);
                MMA_BF16(D[0][nt], ((uint32_t*)&al0), bh[nt]);
                MMA_BF16(D[1][nt], ((uint32_t*)&al1), bh[nt]);
                MMA_BF16(D[0][nt], ((uint32_t*)&ah0), bl[nt]);
                MMA_BF16(D[1][nt], ((uint32_t*)&ah1), bl[nt]);
            }
        }
    }
    float part = 0.0f;
    {
        const int rq = lane >> 2, cq = (lane & 3) * 2;
#pragma unroll
        for (int mt = 0; mt < 2; mt++) {
            int row = w * 32 + mt * 16 + rq;
#pragma unroll
            for (int nt = 0; nt < 2; nt++) {
                int col = nt * 8 + cq;
                part += lds32f(unb + (row * 17 + col) * 4)           * D[mt][nt][0];
                part += lds32f(unb + (row * 17 + col + 1) * 4)       * D[mt][nt][1];
                part += lds32f(unb + ((row + 8) * 17 + col) * 4)     * D[mt][nt][2];
                part += lds32f(unb + ((row + 8) * 17 + col + 1) * 4) * D[mt][nt][3];
            }
        }
    }
#pragma unroll
    for (int o = 16; o > 0; o >>= 1) part += __shfl_xor_sync(0xffffffffu, part, o);
    float* RED = (float*)(smem + SK_RED);
    if (lane == 0) RED[w] = part;
    __syncthreads();
    if (tid == 0) {
        float t = 0.0f;
#pragma unroll
        for (int i = 0; i < 8; i++) t += RED[i];
        atomicAdd(loss, t);
    }
}

extern "C" void kernel_launch(void* const* d_in, const int* in_sizes, int n_in,
                              void* d_out, int out_size)
{
    const float* f    = (const float*)d_in[0];
    const float* head = (const float*)d_in[1];
    const float* W1   = (const float*)d_in[2];
    const float* b1   = (const float*)d_in[3];
    const float* W2   = (const float*)d_in[4];
    const float* b2   = (const float*)d_in[5];
    float* out    = (float*)d_out;
    float* scores = out;
    float* loss   = out + (out_size - 1);

    cudaFuncSetAttribute(merged_kernel, cudaFuncAttributeMaxDynamicSharedMemorySize, MLP_SMEM);
    cudaFuncSetAttribute(sinkhorn_fused_kernel, cudaFuncAttributeMaxDynamicSharedMemorySize, SK_SMEM);

    init_kernel<<<1, 256>>>(loss);
    merged_kernel<<<MLP_GRID + COST_GRID, 384, MLP_SMEM>>>(f, W1, b1, W2, b2, scores);
    kexp_kernel<<<NARC / 256, 256>>>();
    sinkhorn_fused_kernel<<<256, 256, SK_SMEM>>>(scores, head, loss);
}

// round 10
// speedup vs baseline: 1.3730x; 1.3730x over previous
#include <cuda_runtime.h>
#include <cuda_bf16.h>
#include <cuda_fp16.h>
#include <math.h>
#include <stdint.h>

#define NS   16
#define LL   256
#define HH   128
#define LAMF 20.0f
#define EPSF 1e-8f
#define NARC (NS * LL * LL)
#define NCHUNK 8192
#define MLP_GRID2 296
#define COST_GRID (NS * 36)

// -------- scratch --------
__device__ __align__(16) float g_C [NARC];
__device__ unsigned int g_maxabs[NS];
__device__ __align__(16) __nv_bfloat16 g_Kph [NARC];
__device__ __align__(16) __nv_bfloat16 g_Kpl [NARC];
__device__ __align__(16) __nv_bfloat16 g_KMph[NARC];
__device__ __align__(16) __nv_bfloat16 g_KMpl[NARC];

// ================= PTX helpers (baseline sm_103) =================
__device__ __forceinline__ uint32_t smem_u32(const void* p) {
    uint32_t a;
    asm("{ .reg .u64 t; cvta.to.shared.u64 t, %1; cvt.u32.u64 %0, t; }" : "=r"(a) : "l"(p));
    return a;
}
#define LDSM_X4T(r, addr) \
    asm volatile("ldmatrix.sync.aligned.m8n8.x4.trans.shared.b16 {%0,%1,%2,%3}, [%4];" \
        : "=r"((r)[0]), "=r"((r)[1]), "=r"((r)[2]), "=r"((r)[3]) : "r"(addr))
#define MMA_BF16(d, a, b) \
    asm volatile("mma.sync.aligned.m16n8k16.row.col.f32.bf16.bf16.f32 " \
        "{%0,%1,%2,%3}, {%4,%5,%6,%7}, {%8,%9}, {%0,%1,%2,%3};" \
        : "+f"((d)[0]), "+f"((d)[1]), "+f"((d)[2]), "+f"((d)[3]) \
        : "r"((a)[0]), "r"((a)[1]), "r"((a)[2]), "r"((a)[3]), "r"((b)[0]), "r"((b)[1]))
#define MMA_F16(d, a, b) \
    asm volatile("mma.sync.aligned.m16n8k16.row.col.f32.f16.f16.f32 " \
        "{%0,%1,%2,%3}, {%4,%5,%6,%7}, {%8,%9}, {%0,%1,%2,%3};" \
        : "+f"((d)[0]), "+f"((d)[1]), "+f"((d)[2]), "+f"((d)[3]) \
        : "r"((a)[0]), "r"((a)[1]), "r"((a)[2]), "r"((a)[3]), "r"((b)[0]), "r"((b)[1]))
__device__ __forceinline__ void sts32(uint32_t addr, uint32_t v) {
    asm volatile("st.shared.b32 [%0], %1;" :: "r"(addr), "r"(v) : "memory");
}
__device__ __forceinline__ float lds32f(uint32_t addr) {
    float v; asm volatile("ld.shared.f32 %0, [%1];" : "=f"(v) : "r"(addr)); return v;
}
__device__ __forceinline__ void sts32f(uint32_t addr, float v) {
    asm volatile("st.shared.f32 [%0], %1;" :: "r"(addr), "f"(v) : "memory");
}
#define CVT2BF(dst, hi, lo) \
    asm("cvt.rn.bf16x2.f32 %0, %1, %2;" : "=r"(dst) : "f"(hi), "f"(lo))
__device__ __forceinline__ uint32_t pack_bf16(__nv_bfloat16 a, __nv_bfloat16 b) {
    __nv_bfloat162 p = __halves2bfloat162(a, b);
    return *reinterpret_cast<uint32_t*>(&p);
}
__device__ __forceinline__ uint32_t pack_h16f(float a, float b) {
    uint32_t r;
    asm("cvt.rn.f16x2.f32 %0, %1, %2;" : "=r"(r) : "f"(b), "f"(a));
    return r;
}
__device__ __forceinline__ float ftanh(float x) {
    float r; asm("tanh.approx.f32 %0, %1;" : "=f"(r) : "f"(x)); return r;
}

// -------- init --------
__global__ void init_kernel(float* __restrict__ loss) {
    int idx = threadIdx.x;
    if (idx < NS) g_maxabs[idx] = 0u;
    if (idx == 0) *loss = 0.0f;
}

// ============ MERGED: MLP CTAs (0..295, direct-LDG A) + cost CTAs ============
#define PITCHB 272

__global__ void __launch_bounds__(256, 2) merged_kernel(
    const float* __restrict__ f,  const float* __restrict__ W1,
    const float* __restrict__ b1, const float* __restrict__ W2,
    const float* __restrict__ b2, float* __restrict__ scores)
{
    const int tid = threadIdx.x;
    const int w = tid >> 5, lane = tid & 31;

    if (blockIdx.x >= MLP_GRID2) {
        // ================= COST ROLE (576 CTAs, 8 warps) =================
        const int cb = blockIdx.x - MLP_GRID2;
        const int n = cb / 36;
        int tt = cb % 36, bi = 0;
        while (tt >= 8 - bi) { tt -= 8 - bi; bi++; }
        const int bj = bi + tt;
        const float* fn = f + (size_t)n * (LL * LL * HH);
        float* C = g_C + (size_t)n * (LL * LL);
        float lmax = 0.0f;
#pragma unroll 1
        for (int a0 = w * 4; a0 < 1024; a0 += 32) {
            int r = a0 >> 5, cc = a0 & 31;
            int i = bi * 32 + r;
            float4 x[4], y[4];
#pragma unroll
            for (int p = 0; p < 4; p++) {
                int j = bj * 32 + cc + p;
                if (j >= i) {
                    x[p] = __ldg((const float4*)(fn + (size_t)(i * LL + j) * HH) + lane);
                    y[p] = __ldg((const float4*)(fn + (size_t)(j * LL + i) * HH) + lane);
                } else {
                    x[p] = make_float4(0.f, 0.f, 0.f, 0.f);
                    y[p] = x[p];
                }
            }
            float s[4];
#pragma unroll
            for (int p = 0; p < 4; p++)
                s[p] = x[p].x * y[p].x + x[p].y * y[p].y + x[p].z * y[p].z + x[p].w * y[p].w;
#pragma unroll
            for (int o = 16; o > 0; o >>= 1) {
#pragma unroll
                for (int p = 0; p < 4; p++) s[p] += __shfl_xor_sync(0xffffffffu, s[p], o);
            }
            if (lane == 0) {
#pragma unroll
                for (int p = 0; p < 4; p++) {
                    int j = bj * 32 + cc + p;
                    if (j >= i) {
                        C[i * LL + j] = s[p];
                        C[j * LL + i] = s[p];
                        lmax = fmaxf(lmax, fabsf(s[p]));
                    }
                }
            }
        }
        if (lane == 0) atomicMax(&g_maxabs[n], __float_as_uint(lmax));
        return;
    }

    // ================= MLP ROLE: 8 independent warps, A direct from global =====
    __shared__ __align__(16) __half Wh[8 * 16 * 136];   // [k][n] pitch 136
    __shared__ float b1s[128], w2s[128];

    for (int i = tid; i < 16384; i += 256) {
        int k = i >> 7, nn = i & 127;
        Wh[k * 136 + nn] = __float2half_rn(W1[i]);
    }
    if (tid < 128) { b1s[tid] = b1[tid]; w2s[tid] = W2[tid]; }
    __syncthreads();

    const float b2v = __ldg(b2);
    const int g = lane >> 2, t = lane & 3;
    const int lr = lane & 15, lh = lane >> 4;
    const uint32_t wb = smem_u32(Wh);
    const uint32_t b_off = wb + (uint32_t)(lr * PITCHB + lh * 16);

    for (int chunk = blockIdx.x; chunk < NCHUNK; chunk += MLP_GRID2) {
        const float* fb = f + (size_t)chunk * 16384 + (size_t)(w * 16 + g) * 128 + 2 * t;
        // ---- load A: 32x LDG.64, all in flight ----
        float2 af[8][4];
#pragma unroll
        for (int ks = 0; ks < 8; ks++) {
            af[ks][0] = __ldg((const float2*)(fb + ks * 16));
            af[ks][1] = __ldg((const float2*)(fb + ks * 16 + 8 * 128));
            af[ks][2] = __ldg((const float2*)(fb + ks * 16 + 8));
            af[ks][3] = __ldg((const float2*)(fb + ks * 16 + 8 * 128 + 8));
        }
        uint32_t ah[8][4];
#pragma unroll
        for (int ks = 0; ks < 8; ks++)
#pragma unroll
            for (int q = 0; q < 4; q++)
                ah[ks][q] = pack_h16f(af[ks][q].x, af[ks][q].y);

        float D[16][4];
#pragma unroll
        for (int nf = 0; nf < 16; nf++)
#pragma unroll
            for (int q = 0; q < 4; q++) D[nf][q] = 0.0f;

#pragma unroll
        for (int ks = 0; ks < 8; ks++) {
            uint32_t bh[16][2];
#pragma unroll
            for (int p = 0; p < 8; p++) {
                uint32_t r[4];
                LDSM_X4T(r, b_off + ks * (16 * PITCHB) + p * 32);
                bh[2*p][0] = r[0]; bh[2*p][1] = r[1];
                bh[2*p+1][0] = r[2]; bh[2*p+1][1] = r[3];
            }
#pragma unroll
            for (int nf = 0; nf < 16; nf++)
                MMA_F16(D[nf], ah[ks], bh[nf]);
        }

        // ---- epilogue: tanh + dot(w2), reduce over quad ----
        float plo = 0.0f, phi = 0.0f;
#pragma unroll
        for (int nf = 0; nf < 16; nf++) {
            int col = nf * 8 + 2 * t;
            float b1a = b1s[col], b1b = b1s[col + 1];
            float w2a = w2s[col], w2b = w2s[col + 1];
            plo += ftanh(D[nf][0] + b1a) * w2a + ftanh(D[nf][1] + b1b) * w2b;
            phi += ftanh(D[nf][2] + b1a) * w2a + ftanh(D[nf][3] + b1b) * w2b;
        }
        plo += __shfl_xor_sync(0xffffffffu, plo, 1);
        plo += __shfl_xor_sync(0xffffffffu, plo, 2);
        phi += __shfl_xor_sync(0xffffffffu, phi, 1);
        phi += __shfl_xor_sync(0xffffffffu, phi, 2);
        if (t == 0) {
            float* so = scores + (size_t)chunk * 128 + w * 16 + g;
            so[0] = plo + b2v;
            so[8] = phi + b2v;
        }
    }
}

// -------- kexp: K=exp(-LAM*Cn), KM=K*Cn -> split bf16, MMA-A-permuted --------
__global__ void kexp_kernel() {
    int idx = blockIdx.x * blockDim.x + threadIdx.x;
    int n = idx >> 16;
    int r = (idx >> 8) & 255, k = idx & 255;
    float mx = __uint_as_float(g_maxabs[n]);
    float cn = g_C[idx] / (mx + EPSF);
    float kv = __expf(-LAMF * cn);
    float km = kv * cn;
    int mt = r >> 4, rl = r & 15, kt = k >> 4, kl = k & 15;
    int T   = ((rl & 7) << 2) + ((kl & 7) >> 1);
    int reg = (rl >> 3) + ((kl >> 3) << 1);
    int pofs = (n << 16) + (((mt << 4) + kt) << 8) + (T << 3) + (reg << 1) + (kl & 1);
    __nv_bfloat16 kh = __float2bfloat16(kv);
    __nv_bfloat16 mh = __float2bfloat16(km);
    g_Kph [pofs] = kh;
    g_Kpl [pofs] = __float2bfloat16(kv - __bfloat162float(kh));
    g_KMph[pofs] = mh;
    g_KMpl[pofs] = __float2bfloat16(km - __bfloat162float(mh));
}

// ============ fused Sinkhorn (R8 config: 128 CTAs x 512 thr) ============
#define SK_XHI 0
#define SK_XLO 20480
#define SK_UN  40960
#define SK_CN  74752
#define SK_UF  108544
#define SK_RED 142336
#define SK_SMEM 142400

template<bool STORE_U>
__device__ __noinline__ void sink_phase(
    const uint4* __restrict__ Ah, const uint4* __restrict__ Al,
    uint32_t xhi, uint32_t xlo, uint32_t nmb, uint32_t ufb, int w, int lane)
{
    float D[4][4];
#pragma unroll
    for (int j = 0; j < 4; j++)
#pragma unroll
        for (int q = 0; q < 4; q++) D[j][q] = 0.0f;

    const int lr = lane & 15, lh = lane >> 4;
    const uint32_t bhb = xhi + lr * 80 + lh * 16;
    const uint32_t blb = xlo + lr * 80 + lh * 16;
#pragma unroll 4
    for (int kt = 0; kt < 16; kt++) {
        uint4 ah = Ah[(size_t)(w * 16 + kt) * 32 + lane];
        uint4 al = Al[(size_t)(w * 16 + kt) * 32 + lane];
        uint32_t bh[4][2], bl[4][2], r[4];
        LDSM_X4T(r, bhb + kt * 1280);      bh[0][0]=r[0]; bh[0][1]=r[1]; bh[1][0]=r[2]; bh[1][1]=r[3];
        LDSM_X4T(r, bhb + kt * 1280 + 32); bh[2][0]=r[0]; bh[2][1]=r[1]; bh[3][0]=r[2]; bh[3][1]=r[3];
        LDSM_X4T(r, blb + kt * 1280);      bl[0][0]=r[0]; bl[0][1]=r[1]; bl[1][0]=r[2]; bl[1][1]=r[3];
        LDSM_X4T(r, blb + kt * 1280 + 32); bl[2][0]=r[0]; bl[2][1]=r[1]; bl[3][0]=r[2]; bl[3][1]=r[3];
#pragma unroll
        for (int nt = 0; nt < 4; nt++) {
            MMA_BF16(D[nt], ((uint32_t*)&ah), bh[nt]);
            MMA_BF16(D[nt], ((uint32_t*)&al), bh[nt]);
            MMA_BF16(D[nt], ((uint32_t*)&ah), bl[nt]);
        }
    }
    __syncthreads();
    const int rq = lane >> 2, cq = (lane & 3) * 2;
    const int row = w * 16 + rq;
#pragma unroll
    for (int nt = 0; nt < 4; nt++) {
        int col = nt * 8 + cq;
        float n0 = lds32f(nmb + (row * 33 + col) * 4);
        float n1 = lds32f(nmb + (row * 33 + col + 1) * 4);
        float n2 = lds32f(nmb + ((row + 8) * 33 + col) * 4);
        float n3 = lds32f(nmb + ((row + 8) * 33 + col + 1) * 4);
        float o0 = __fdividef(n0, D[nt][0] + EPSF);
        float o1 = __fdividef(n1, D[nt][1] + EPSF);
        float o2 = __fdividef(n2, D[nt][2] + EPSF);
        float o3 = __fdividef(n3, D[nt][3] + EPSF);
        uint32_t h01, h23, l01, l23;
        CVT2BF(h01, o1, o0);
        CVT2BF(h23, o3, o2);
        float l0 = o0 - __uint_as_float(h01 << 16);
        float l1 = o1 - __uint_as_float(h01 & 0xffff0000u);
        float l2 = o2 - __uint_as_float(h23 << 16);
        float l3 = o3 - __uint_as_float(h23 & 0xffff0000u);
        CVT2BF(l01, l1, l0);
        CVT2BF(l23, l3, l2);
        sts32(xhi + row * 80 + col * 2, h01);
        sts32(xhi + (row + 8) * 80 + col * 2, h23);
        sts32(xlo + row * 80 + col * 2, l01);
        sts32(xlo + (row + 8) * 80 + col * 2, l23);
        if (STORE_U) {
            sts32f(ufb + (row * 33 + col) * 4, o0);
            sts32f(ufb + (row * 33 + col + 1) * 4, o1);
            sts32f(ufb + ((row + 8) * 33 + col) * 4, o2);
            sts32f(ufb + ((row + 8) * 33 + col + 1) * 4, o3);
        }
    }
    __syncthreads();
}

__global__ void __launch_bounds__(512, 1) sinkhorn_fused_kernel(
    const float* __restrict__ scores, const float* __restrict__ head,
    float* __restrict__ loss)
{
    extern __shared__ __align__(16) char smem[];
    const uint32_t sb = smem_u32(smem);
    const int tid = threadIdx.x, lane = tid & 31, w = tid >> 5;
    const int n = blockIdx.x >> 3, c0 = (blockIdx.x & 7) * 32;

    float* UN = (float*)(smem + SK_UN);
    float* CN = (float*)(smem + SK_CN);
#pragma unroll
    for (int q = 0; q < 2; q++) {
        int p = w * 2 + q;
        const float* row = scores + ((size_t)(n * 256 + c0 + p)) * 256;
        float4 v0 = *(const float4*)(row + lane * 4);
        float4 v1 = *(const float4*)(row + 128 + lane * 4);
        float m = fmaxf(fmaxf(fmaxf(v0.x, v0.y), fmaxf(v0.z, v0.w)),
                        fmaxf(fmaxf(v1.x, v1.y), fmaxf(v1.z, v1.w)));
#pragma unroll
        for (int o = 16; o > 0; o >>= 1) m = fmaxf(m, __shfl_xor_sync(0xffffffffu, m, o));
        float e[8];
        e[0] = __expf(v0.x - m); e[1] = __expf(v0.y - m);
        e[2] = __expf(v0.z - m); e[3] = __expf(v0.w - m);
        e[4] = __expf(v1.x - m); e[5] = __expf(v1.y - m);
        e[6] = __expf(v1.z - m); e[7] = __expf(v1.w - m);
        float sum = e[0]+e[1]+e[2]+e[3]+e[4]+e[5]+e[6]+e[7];
#pragma unroll
        for (int o = 16; o > 0; o >>= 1) sum += __shfl_xor_sync(0xffffffffu, sum, o);
        float inv = __fdividef(1.0f, sum);
#pragma unroll
        for (int k = 0; k < 4; k++) UN[(lane * 4 + k) * 33 + p]       = e[k] * inv;
#pragma unroll
        for (int k = 0; k < 4; k++) UN[(128 + lane * 4 + k) * 33 + p] = e[4 + k] * inv;

        const float* hrow = head + ((size_t)(n * 256 + c0 + p)) * 256;
        float4 h0 = *(const float4*)(hrow + lane * 4);
        float4 h1 = *(const float4*)(hrow + 128 + lane * 4);
        float he[8] = { h0.x + EPSF, h0.y + EPSF, h0.z + EPSF, h0.w + EPSF,
                        h1.x + EPSF, h1.y + EPSF, h1.z + EPSF, h1.w + EPSF };
        float hsum = he[0]+he[1]+he[2]+he[3]+he[4]+he[5]+he[6]+he[7];
#pragma unroll
        for (int o = 16; o > 0; o >>= 1) hsum += __shfl_xor_sync(0xffffffffu, hsum, o);
        float hinv = __fdividef(1.0f, hsum);
#pragma unroll
        for (int k = 0; k < 4; k++) CN[(lane * 4 + k) * 33 + p]       = he[k] * hinv;
#pragma unroll
        for (int k = 0; k < 4; k++) CN[(128 + lane * 4 + k) * 33 + p] = he[4 + k] * hinv;
    }
    const uint32_t HV = pack_bf16(__float2bfloat16(1.0f / 256.0f),
                                  __float2bfloat16(1.0f / 256.0f));
    for (int i = tid; i < 5120; i += 512) {
        ((uint32_t*)(smem + SK_XHI))[i] = HV;
        ((uint32_t*)(smem + SK_XLO))[i] = 0u;
    }
    __syncthreads();

    const uint4* Kh  = (const uint4*)g_Kph  + (size_t)n * 8192;
    const uint4* Kl  = (const uint4*)g_Kpl  + (size_t)n * 8192;
    const uint4* Mh  = (const uint4*)g_KMph + (size_t)n * 8192;
    const uint4* Ml  = (const uint4*)g_KMpl + (size_t)n * 8192;
    const uint32_t xhi = sb + SK_XHI, xlo = sb + SK_XLO;
    const uint32_t unb = sb + SK_UN, cnb = sb + SK_CN, ufb = sb + SK_UF;

#pragma unroll 1
    for (int it = 0; it < 19; it++) {
        sink_phase<false>(Kh, Kl, xhi, xlo, cnb, ufb, w, lane);
        sink_phase<false>(Kh, Kl, xhi, xlo, unb, ufb, w, lane);
    }
    sink_phase<false>(Kh, Kl, xhi, xlo, cnb, ufb, w, lane);
    sink_phase<true >(Kh, Kl, xhi, xlo, unb, ufb, w, lane);
    sink_phase<false>(Kh, Kl, xhi, xlo, cnb, ufb, w, lane);

    float D[4][4];
#pragma unroll
    for (int j = 0; j < 4; j++)
#pragma unroll
        for (int q = 0; q < 4; q++) D[j][q] = 0.0f;
    {
        const int lr = lane & 15, lh = lane >> 4;
        const uint32_t bhb = xhi + lr * 80 + lh * 16;
        const uint32_t blb = xlo + lr * 80 + lh * 16;
#pragma unroll 4
        for (int kt = 0; kt < 16; kt++) {
            uint4 ah = Mh[(size_t)(w * 16 + kt) * 32 + lane];
            uint4 al = Ml[(size_t)(w * 16 + kt) * 32 + lane];
            uint32_t bh[4][2], bl[4][2], r[4];
            LDSM_X4T(r, bhb + kt * 1280);      bh[0][0]=r[0]; bh[0][1]=r[1]; bh[1][0]=r[2]; bh[1][1]=r[3];
            LDSM_X4T(r, bhb + kt * 1280 + 32); bh[2][0]=r[0]; bh[2][1]=r[1]; bh[3][0]=r[2]; bh[3][1]=r[3];
            LDSM_X4T(r, blb + kt * 1280);      bl[0][0]=r[0]; bl[0][1]=r[1]; bl[1][0]=r[2]; bl[1][1]=r[3];
            LDSM_X4T(r, blb + kt * 1280 + 32); bl[2][0]=r[0]; bl[2][1]=r[1]; bl[3][0]=r[2]; bl[3][1]=r[3];
#pragma unroll
            for (int nt = 0; nt < 4; nt++) {
                MMA_BF16(D[nt], ((uint32_t*)&ah), bh[nt]);
                MMA_BF16(D[nt], ((uint32_t*)&al), bh[nt]);
                MMA_BF16(D[nt], ((uint32_t*)&ah), bl[nt]);
            }
        }
    }
    float part = 0.0f;
    {
        const int rq = lane >> 2, cq = (lane & 3) * 2;
        const int row = w * 16 + rq;
#pragma unroll
        for (int nt = 0; nt < 4; nt++) {
            int col = nt * 8 + cq;
            part += lds32f(ufb + (row * 33 + col) * 4)           * D[nt][0];
            part += lds32f(ufb + (row * 33 + col + 1) * 4)       * D[nt][1];
            part += lds32f(ufb + ((row + 8) * 33 + col) * 4)     * D[nt][2];
            part += lds32f(ufb + ((row + 8) * 33 + col + 1) * 4) * D[nt][3];
        }
    }
#pragma unroll
    for (int o = 16; o > 0; o >>= 1) part += __shfl_xor_sync(0xffffffffu, part, o);
    float* RED = (float*)(smem + SK_RED);
    if (lane == 0) RED[w] = part;
    __syncthreads();
    if (tid == 0) {
        float t = 0.0f;
#pragma unroll
        for (int i = 0; i < 16; i++) t += RED[i];
        atomicAdd(loss, t);
    }
}

extern "C" void kernel_launch(void* const* d_in, const int* in_sizes, int n_in,
                              void* d_out, int out_size)
{
    const float* f    = (const float*)d_in[0];
    const float* head = (const float*)d_in[1];
    const float* W1   = (const float*)d_in[2];
    const float* b1   = (const float*)d_in[3];
    const float* W2   = (const float*)d_in[4];
    const float* b2   = (const float*)d_in[5];
    float* out    = (float*)d_out;
    float* scores = out;
    float* loss   = out + (out_size - 1);

    cudaFuncSetAttribute(sinkhorn_fused_kernel, cudaFuncAttributeMaxDynamicSharedMemorySize, SK_SMEM);

    init_kernel<<<1, 256>>>(loss);
    merged_kernel<<<MLP_GRID2 + COST_GRID, 256>>>(f, W1, b1, W2, b2, scores);
    kexp_kernel<<<NARC / 256, 256>>>();
    sinkhorn_fused_kernel<<<128, 512, SK_SMEM>>>(scores, head, loss);
}

// round 11
// speedup vs baseline: 1.5709x; 1.1442x over previous
#include <cuda_runtime.h>
#include <cuda_bf16.h>
#include <cuda_fp16.h>
#include <math.h>
#include <stdint.h>

#define NS   16
#define LL   256
#define HH   128
#define LAMF 20.0f
#define EPSF 1e-8f
#define NARC (NS * LL * LL)
#define NCHUNK 8192
#define MLP_GRID2 296
#define COST_GRID (NS * 36)

// -------- scratch --------
__device__ __align__(16) float g_C [NARC];
__device__ unsigned int g_maxabs[NS];
__device__ __align__(16) __nv_bfloat16 g_Kph [NARC];
__device__ __align__(16) __nv_bfloat16 g_Kpl [NARC];
__device__ __align__(16) __nv_bfloat16 g_KMph[NARC];
__device__ __align__(16) __nv_bfloat16 g_KMpl[NARC];

// ================= PTX helpers (baseline sm_103) =================
__device__ __forceinline__ uint32_t smem_u32(const void* p) {
    uint32_t a;
    asm("{ .reg .u64 t; cvta.to.shared.u64 t, %1; cvt.u32.u64 %0, t; }" : "=r"(a) : "l"(p));
    return a;
}
#define LDSM_X4T(r, addr) \
    asm volatile("ldmatrix.sync.aligned.m8n8.x4.trans.shared.b16 {%0,%1,%2,%3}, [%4];" \
        : "=r"((r)[0]), "=r"((r)[1]), "=r"((r)[2]), "=r"((r)[3]) : "r"(addr))
#define MMA_BF16(d, a, b) \
    asm volatile("mma.sync.aligned.m16n8k16.row.col.f32.bf16.bf16.f32 " \
        "{%0,%1,%2,%3}, {%4,%5,%6,%7}, {%8,%9}, {%0,%1,%2,%3};" \
        : "+f"((d)[0]), "+f"((d)[1]), "+f"((d)[2]), "+f"((d)[3]) \
        : "r"((a)[0]), "r"((a)[1]), "r"((a)[2]), "r"((a)[3]), "r"((b)[0]), "r"((b)[1]))
#define MMA_F16(d, a, b) \
    asm volatile("mma.sync.aligned.m16n8k16.row.col.f32.f16.f16.f32 " \
        "{%0,%1,%2,%3}, {%4,%5,%6,%7}, {%8,%9}, {%0,%1,%2,%3};" \
        : "+f"((d)[0]), "+f"((d)[1]), "+f"((d)[2]), "+f"((d)[3]) \
        : "r"((a)[0]), "r"((a)[1]), "r"((a)[2]), "r"((a)[3]), "r"((b)[0]), "r"((b)[1]))
__device__ __forceinline__ void sts32(uint32_t addr, uint32_t v) {
    asm volatile("st.shared.b32 [%0], %1;" :: "r"(addr), "r"(v) : "memory");
}
__device__ __forceinline__ float lds32f(uint32_t addr) {
    float v; asm volatile("ld.shared.f32 %0, [%1];" : "=f"(v) : "r"(addr)); return v;
}
__device__ __forceinline__ void sts32f(uint32_t addr, float v) {
    asm volatile("st.shared.f32 [%0], %1;" :: "r"(addr), "f"(v) : "memory");
}
#define CVT2BF(dst, hi, lo) \
    asm("cvt.rn.bf16x2.f32 %0, %1, %2;" : "=r"(dst) : "f"(hi), "f"(lo))
__device__ __forceinline__ uint32_t pack_bf16(__nv_bfloat16 a, __nv_bfloat16 b) {
    __nv_bfloat162 p = __halves2bfloat162(a, b);
    return *reinterpret_cast<uint32_t*>(&p);
}
__device__ __forceinline__ uint32_t pack_h16f(float a, float b) {
    uint32_t r;
    asm("cvt.rn.f16x2.f32 %0, %1, %2;" : "=r"(r) : "f"(b), "f"(a));
    return r;
}
__device__ __forceinline__ float ftanh(float x) {
    float r; asm("tanh.approx.f32 %0, %1;" : "=f"(r) : "f"(x)); return r;
}

// -------- init --------
__global__ void init_kernel(float* __restrict__ loss) {
    int idx = threadIdx.x;
    if (idx < NS) g_maxabs[idx] = 0u;
    if (idx == 0) *loss = 0.0f;
}

// ============ MERGED: MLP CTAs (0..295, direct-LDG A) + cost CTAs ============
#define PITCHB 272

__global__ void __launch_bounds__(256, 2) merged_kernel(
    const float* __restrict__ f,  const float* __restrict__ W1,
    const float* __restrict__ b1, const float* __restrict__ W2,
    const float* __restrict__ b2, float* __restrict__ scores)
{
    const int tid = threadIdx.x;
    const int w = tid >> 5, lane = tid & 31;

    if (blockIdx.x >= MLP_GRID2) {
        // ================= COST ROLE =================
        const int cb = blockIdx.x - MLP_GRID2;
        const int n = cb / 36;
        int tt = cb % 36, bi = 0;
        while (tt >= 8 - bi) { tt -= 8 - bi; bi++; }
        const int bj = bi + tt;
        const float* fn = f + (size_t)n * (LL * LL * HH);
        float* C = g_C + (size_t)n * (LL * LL);
        float lmax = 0.0f;
#pragma unroll 1
        for (int a0 = w * 4; a0 < 1024; a0 += 32) {
            int r = a0 >> 5, cc = a0 & 31;
            int i = bi * 32 + r;
            float4 x[4], y[4];
#pragma unroll
            for (int p = 0; p < 4; p++) {
                int j = bj * 32 + cc + p;
                if (j >= i) {
                    x[p] = __ldg((const float4*)(fn + (size_t)(i * LL + j) * HH) + lane);
                    y[p] = __ldg((const float4*)(fn + (size_t)(j * LL + i) * HH) + lane);
                } else {
                    x[p] = make_float4(0.f, 0.f, 0.f, 0.f);
                    y[p] = x[p];
                }
            }
            float s[4];
#pragma unroll
            for (int p = 0; p < 4; p++)
                s[p] = x[p].x * y[p].x + x[p].y * y[p].y + x[p].z * y[p].z + x[p].w * y[p].w;
#pragma unroll
            for (int o = 16; o > 0; o >>= 1) {
#pragma unroll
                for (int p = 0; p < 4; p++) s[p] += __shfl_xor_sync(0xffffffffu, s[p], o);
            }
            if (lane == 0) {
#pragma unroll
                for (int p = 0; p < 4; p++) {
                    int j = bj * 32 + cc + p;
                    if (j >= i) {
                        C[i * LL + j] = s[p];
                        C[j * LL + i] = s[p];
                        lmax = fmaxf(lmax, fabsf(s[p]));
                    }
                }
            }
        }
        if (lane == 0) atomicMax(&g_maxabs[n], __float_as_uint(lmax));
        return;
    }

    // ================= MLP ROLE: 8 independent warps, A direct from global =====
    __shared__ __align__(16) __half Wh[8 * 16 * 136];
    __shared__ float b1s[128], w2s[128];

    for (int i = tid; i < 16384; i += 256) {
        int k = i >> 7, nn = i & 127;
        Wh[k * 136 + nn] = __float2half_rn(W1[i]);
    }
    if (tid < 128) { b1s[tid] = b1[tid]; w2s[tid] = W2[tid]; }
    __syncthreads();

    const float b2v = __ldg(b2);
    const int g = lane >> 2, t = lane & 3;
    const int lr = lane & 15, lh = lane >> 4;
    const uint32_t wb = smem_u32(Wh);
    const uint32_t b_off = wb + (uint32_t)(lr * PITCHB + lh * 16);

    for (int chunk = blockIdx.x; chunk < NCHUNK; chunk += MLP_GRID2) {
        const float* fb = f + (size_t)chunk * 16384 + (size_t)(w * 16 + g) * 128 + 2 * t;
        float2 af[8][4];
#pragma unroll
        for (int ks = 0; ks < 8; ks++) {
            af[ks][0] = __ldg((const float2*)(fb + ks * 16));
            af[ks][1] = __ldg((const float2*)(fb + ks * 16 + 8 * 128));
            af[ks][2] = __ldg((const float2*)(fb + ks * 16 + 8));
            af[ks][3] = __ldg((const float2*)(fb + ks * 16 + 8 * 128 + 8));
        }
        uint32_t ah[8][4];
#pragma unroll
        for (int ks = 0; ks < 8; ks++)
#pragma unroll
            for (int q = 0; q < 4; q++)
                ah[ks][q] = pack_h16f(af[ks][q].x, af[ks][q].y);

        float D[16][4];
#pragma unroll
        for (int nf = 0; nf < 16; nf++)
#pragma unroll
            for (int q = 0; q < 4; q++) D[nf][q] = 0.0f;

#pragma unroll
        for (int ks = 0; ks < 8; ks++) {
            uint32_t bh[16][2];
#pragma unroll
            for (int p = 0; p < 8; p++) {
                uint32_t r[4];
                LDSM_X4T(r, b_off + ks * (16 * PITCHB) + p * 32);
                bh[2*p][0] = r[0]; bh[2*p][1] = r[1];
                bh[2*p+1][0] = r[2]; bh[2*p+1][1] = r[3];
            }
#pragma unroll
            for (int nf = 0; nf < 16; nf++)
                MMA_F16(D[nf], ah[ks], bh[nf]);
        }

        float plo = 0.0f, phi = 0.0f;
#pragma unroll
        for (int nf = 0; nf < 16; nf++) {
            int col = nf * 8 + 2 * t;
            float b1a = b1s[col], b1b = b1s[col + 1];
            float w2a = w2s[col], w2b = w2s[col + 1];
            plo += ftanh(D[nf][0] + b1a) * w2a + ftanh(D[nf][1] + b1b) * w2b;
            phi += ftanh(D[nf][2] + b1a) * w2a + ftanh(D[nf][3] + b1b) * w2b;
        }
        plo += __shfl_xor_sync(0xffffffffu, plo, 1);
        plo += __shfl_xor_sync(0xffffffffu, plo, 2);
        phi += __shfl_xor_sync(0xffffffffu, phi, 1);
        phi += __shfl_xor_sync(0xffffffffu, phi, 2);
        if (t == 0) {
            float* so = scores + (size_t)chunk * 128 + w * 16 + g;
            so[0] = plo + b2v;
            so[8] = phi + b2v;
        }
    }
}

// -------- kexp: K=exp(-LAM*Cn), KM=K*Cn -> split bf16, MMA-A-permuted --------
__global__ void kexp_kernel() {
    int idx = blockIdx.x * blockDim.x + threadIdx.x;
    int n = idx >> 16;
    int r = (idx >> 8) & 255, k = idx & 255;
    float mx = __uint_as_float(g_maxabs[n]);
    float cn = g_C[idx] / (mx + EPSF);
    float kv = __expf(-LAMF * cn);
    float km = kv * cn;
    int mt = r >> 4, rl = r & 15, kt = k >> 4, kl = k & 15;
    int T   = ((rl & 7) << 2) + ((kl & 7) >> 1);
    int reg = (rl >> 3) + ((kl >> 3) << 1);
    int pofs = (n << 16) + (((mt << 4) + kt) << 8) + (T << 3) + (reg << 1) + (kl & 1);
    __nv_bfloat16 kh = __float2bfloat16(kv);
    __nv_bfloat16 mh = __float2bfloat16(km);
    g_Kph [pofs] = kh;
    g_Kpl [pofs] = __float2bfloat16(kv - __bfloat162float(kh));
    g_KMph[pofs] = mh;
    g_KMpl[pofs] = __float2bfloat16(km - __bfloat162float(mh));
}

// ============ fused Sinkhorn: 2-term (Khi+Klo)@Xhi, no Xlo ============
#define SK_XHI 0
#define SK_UN  20480
#define SK_CN  54272
#define SK_UF  88064
#define SK_RED 121856
#define SK_SMEM 121920

template<bool STORE_U>
__device__ __noinline__ void sink_phase(
    const uint4* __restrict__ Ah, const uint4* __restrict__ Al,
    uint32_t xhi, uint32_t nmb, uint32_t ufb, int w, int lane)
{
    float D[4][4];
#pragma unroll
    for (int j = 0; j < 4; j++)
#pragma unroll
        for (int q = 0; q < 4; q++) D[j][q] = 0.0f;

    const int lr = lane & 15, lh = lane >> 4;
    const uint32_t bhb = xhi + lr * 80 + lh * 16;
#pragma unroll 4
    for (int kt = 0; kt < 16; kt++) {
        uint4 ah = Ah[(size_t)(w * 16 + kt) * 32 + lane];
        uint4 al = Al[(size_t)(w * 16 + kt) * 32 + lane];
        uint32_t bh[4][2], r[4];
        LDSM_X4T(r, bhb + kt * 1280);      bh[0][0]=r[0]; bh[0][1]=r[1]; bh[1][0]=r[2]; bh[1][1]=r[3];
        LDSM_X4T(r, bhb + kt * 1280 + 32); bh[2][0]=r[0]; bh[2][1]=r[1]; bh[3][0]=r[2]; bh[3][1]=r[3];
#pragma unroll
        for (int nt = 0; nt < 4; nt++) {
            MMA_BF16(D[nt], ((uint32_t*)&ah), bh[nt]);
            MMA_BF16(D[nt], ((uint32_t*)&al), bh[nt]);
        }
    }
    __syncthreads();
    const int rq = lane >> 2, cq = (lane & 3) * 2;
    const int row = w * 16 + rq;
#pragma unroll
    for (int nt = 0; nt < 4; nt++) {
        int col = nt * 8 + cq;
        float n0 = lds32f(nmb + (row * 33 + col) * 4);
        float n1 = lds32f(nmb + (row * 33 + col + 1) * 4);
        float n2 = lds32f(nmb + ((row + 8) * 33 + col) * 4);
        float n3 = lds32f(nmb + ((row + 8) * 33 + col + 1) * 4);
        float o0 = __fdividef(n0, D[nt][0] + EPSF);
        float o1 = __fdividef(n1, D[nt][1] + EPSF);
        float o2 = __fdividef(n2, D[nt][2] + EPSF);
        float o3 = __fdividef(n3, D[nt][3] + EPSF);
        uint32_t h01, h23;
        CVT2BF(h01, o1, o0);
        CVT2BF(h23, o3, o2);
        sts32(xhi + row * 80 + col * 2, h01);
        sts32(xhi + (row + 8) * 80 + col * 2, h23);
        if (STORE_U) {
            sts32f(ufb + (row * 33 + col) * 4, o0);
            sts32f(ufb + (row * 33 + col + 1) * 4, o1);
            sts32f(ufb + ((row + 8) * 33 + col) * 4, o2);
            sts32f(ufb + ((row + 8) * 33 + col + 1) * 4, o3);
        }
    }
    __syncthreads();
}

__global__ void __launch_bounds__(512, 1) sinkhorn_fused_kernel(
    const float* __restrict__ scores, const float* __restrict__ head,
    float* __restrict__ loss)
{
    extern __shared__ __align__(16) char smem[];
    const uint32_t sb = smem_u32(smem);
    const int tid = threadIdx.x, lane = tid & 31, w = tid >> 5;
    const int n = blockIdx.x >> 3, c0 = (blockIdx.x & 7) * 32;

    float* UN = (float*)(smem + SK_UN);
    float* CN = (float*)(smem + SK_CN);
#pragma unroll
    for (int q = 0; q < 2; q++) {
        int p = w * 2 + q;
        const float* row = scores + ((size_t)(n * 256 + c0 + p)) * 256;
        float4 v0 = *(const float4*)(row + lane * 4);
        float4 v1 = *(const float4*)(row + 128 + lane * 4);
        float m = fmaxf(fmaxf(fmaxf(v0.x, v0.y), fmaxf(v0.z, v0.w)),
                        fmaxf(fmaxf(v1.x, v1.y), fmaxf(v1.z, v1.w)));
#pragma unroll
        for (int o = 16; o > 0; o >>= 1) m = fmaxf(m, __shfl_xor_sync(0xffffffffu, m, o));
        float e[8];
        e[0] = __expf(v0.x - m); e[1] = __expf(v0.y - m);
        e[2] = __expf(v0.z - m); e[3] = __expf(v0.w - m);
        e[4] = __expf(v1.x - m); e[5] = __expf(v1.y - m);
        e[6] = __expf(v1.z - m); e[7] = __expf(v1.w - m);
        float sum = e[0]+e[1]+e[2]+e[3]+e[4]+e[5]+e[6]+e[7];
#pragma unroll
        for (int o = 16; o > 0; o >>= 1) sum += __shfl_xor_sync(0xffffffffu, sum, o);
        float inv = __fdividef(1.0f, sum);
#pragma unroll
        for (int k = 0; k < 4; k++) UN[(lane * 4 + k) * 33 + p]       = e[k] * inv;
#pragma unroll
        for (int k = 0; k < 4; k++) UN[(128 + lane * 4 + k) * 33 + p] = e[4 + k] * inv;

        const float* hrow = head + ((size_t)(n * 256 + c0 + p)) * 256;
        float4 h0 = *(const float4*)(hrow + lane * 4);
        float4 h1 = *(const float4*)(hrow + 128 + lane * 4);
        float he[8] = { h0.x + EPSF, h0.y + EPSF, h0.z + EPSF, h0.w + EPSF,
                        h1.x + EPSF, h1.y + EPSF, h1.z + EPSF, h1.w + EPSF };
        float hsum = he[0]+he[1]+he[2]+he[3]+he[4]+he[5]+he[6]+he[7];
#pragma unroll
        for (int o = 16; o > 0; o >>= 1) hsum += __shfl_xor_sync(0xffffffffu, hsum, o);
        float hinv = __fdividef(1.0f, hsum);
#pragma unroll
        for (int k = 0; k < 4; k++) CN[(lane * 4 + k) * 33 + p]       = he[k] * hinv;
#pragma unroll
        for (int k = 0; k < 4; k++) CN[(128 + lane * 4 + k) * 33 + p] = he[4 + k] * hinv;
    }
    const uint32_t HV = pack_bf16(__float2bfloat16(1.0f / 256.0f),
                                  __float2bfloat16(1.0f / 256.0f));
    for (int i = tid; i < 5120; i += 512)
        ((uint32_t*)(smem + SK_XHI))[i] = HV;
    __syncthreads();

    const uint4* Kh  = (const uint4*)g_Kph  + (size_t)n * 8192;
    const uint4* Kl  = (const uint4*)g_Kpl  + (size_t)n * 8192;
    const uint4* Mh  = (const uint4*)g_KMph + (size_t)n * 8192;
    const uint4* Ml  = (const uint4*)g_KMpl + (size_t)n * 8192;
    const uint32_t xhi = sb + SK_XHI;
    const uint32_t unb = sb + SK_UN, cnb = sb + SK_CN, ufb = sb + SK_UF;

#pragma unroll 1
    for (int it = 0; it < 19; it++) {
        sink_phase<false>(Kh, Kl, xhi, cnb, ufb, w, lane);
        sink_phase<false>(Kh, Kl, xhi, unb, ufb, w, lane);
    }
    sink_phase<false>(Kh, Kl, xhi, cnb, ufb, w, lane);
    sink_phase<true >(Kh, Kl, xhi, unb, ufb, w, lane);
    sink_phase<false>(Kh, Kl, xhi, cnb, ufb, w, lane);

    // loss partial: sum uF .* (KM @ v)
    float D[4][4];
#pragma unroll
    for (int j = 0; j < 4; j++)
#pragma unroll
        for (int q = 0; q < 4; q++) D[j][q] = 0.0f;
    {
        const int lr = lane & 15, lh = lane >> 4;
        const uint32_t bhb = xhi + lr * 80 + lh * 16;
#pragma unroll 4
        for (int kt = 0; kt < 16; kt++) {
            uint4 ah = Mh[(size_t)(w * 16 + kt) * 32 + lane];
            uint4 al = Ml[(size_t)(w * 16 + kt) * 32 + lane];
            uint32_t bh[4][2], r[4];
            LDSM_X4T(r, bhb + kt * 1280);      bh[0][0]=r[0]; bh[0][1]=r[1]; bh[1][0]=r[2]; bh[1][1]=r[3];
            LDSM_X4T(r, bhb + kt * 1280 + 32); bh[2][0]=r[0]; bh[2][1]=r[1]; bh[3][0]=r[2]; bh[3][1]=r[3];
#pragma unroll
            for (int nt = 0; nt < 4; nt++) {
                MMA_BF16(D[nt], ((uint32_t*)&ah), bh[nt]);
                MMA_BF16(D[nt], ((uint32_t*)&al), bh[nt]);
            }
        }
    }
    float part = 0.0f;
    {
        const int rq = lane >> 2, cq = (lane & 3) * 2;
        const int row = w * 16 + rq;
#pragma unroll
        for (int nt = 0; nt < 4; nt++) {
            int col = nt * 8 + cq;
            part += lds32f(ufb + (row * 33 + col) * 4)           * D[nt][0];
            part += lds32f(ufb + (row * 33 + col + 1) * 4)       * D[nt][1];
            part += lds32f(ufb + ((row + 8) * 33 + col) * 4)     * D[nt][2];
            part += lds32f(ufb + ((row + 8) * 33 + col + 1) * 4) * D[nt][3];
        }
    }
#pragma unroll
    for (int o = 16; o > 0; o >>= 1) part += __shfl_xor_sync(0xffffffffu, part, o);
    float* RED = (float*)(smem + SK_RED);
    if (lane == 0) RED[w] = part;
    __syncthreads();
    if (tid == 0) {
        float t = 0.0f;
#pragma unroll
        for (int i = 0; i < 16; i++) t += RED[i];
        atomicAdd(loss, t);
    }
}

extern "C" void kernel_launch(void* const* d_in, const int* in_sizes, int n_in,
                              void* d_out, int out_size)
{
    const float* f    = (const float*)d_in[0];
    const float* head = (const float*)d_in[1];
    const float* W1   = (const float*)d_in[2];
    const float* b1   = (const float*)d_in[3];
    const float* W2   = (const float*)d_in[4];
    const float* b2   = (const float*)d_in[5];
    float* out    = (float*)d_out;
    float* scores = out;
    float* loss   = out + (out_size - 1);

    cudaFuncSetAttribute(sinkhorn_fused_kernel, cudaFuncAttributeMaxDynamicSharedMemorySize, SK_SMEM);

    init_kernel<<<1, 256>>>(loss);
    merged_kernel<<<MLP_GRID2 + COST_GRID, 256>>>(f, W1, b1, W2, b2, scores);
    kexp_kernel<<<NARC / 256, 256>>>();
    sinkhorn_fused_kernel<<<128, 512, SK_SMEM>>>(scores, head, loss);
}